// round 15
// baseline (speedup 1.0000x reference)
#include <cuda_runtime.h>
#include <cstdint>
#include <cstddef>

#define NC    4
#define CC    64
#define DC    192
#define TPAD  196
#define GPAD  68
#define QQ    512
#define ND    (NC*DC)
#define IDIM  768
#define EPSF  1e-8f
#define SQ194 194
#define KHALF 384

__device__ float g_hmP[2][NC*CC*DC];    // gemm partial (no bias), K halves
__device__ float g_hqP[2][QQ*ND];
__device__ float g_hatm[NC*CC*DC];      // combined (written in prep_dotq)
__device__ float g_G[NC*CC*CC];
__device__ float g_mu[NC*CC];
__device__ float g_sxx[NC*CC];
__device__ float g_dq0[QQ*NC*CC];
__device__ float g_S1[QQ*NC];
__device__ float g_ss[QQ*NC];

typedef unsigned long long u64;
__device__ __forceinline__ void f2unpack(u64 v, float& lo, float& hi) {
    asm("mov.b64 {%0, %1}, %2;" : "=f"(lo), "=f"(hi) : "l"(v));
}
__device__ __forceinline__ u64 f2dup(float a) {
    u64 r;
    asm("mov.b64 %0, {%1, %1};" : "=l"(r) : "f"(a));
    return r;
}
__device__ __forceinline__ u64 ffma2(u64 a, u64 b, u64 c) {
    u64 d;
    asm("fma.rn.f32x2 %0, %1, %2, %3;" : "=l"(d) : "l"(a), "l"(b), "l"(c));
    return d;
}
__device__ __forceinline__ void cpa16(unsigned dst, const void* src) {
    asm volatile("cp.async.ca.shared.global [%0], [%1], 16;" :: "r"(dst), "l"(src));
}
__device__ __forceinline__ void cpa4(unsigned dst, const void* src) {
    asm volatile("cp.async.ca.shared.global [%0], [%1], 4;" :: "r"(dst), "l"(src));
}
__device__ __forceinline__ void cpa_commit() {
    asm volatile("cp.async.commit_group;" ::: "memory");
}
__device__ __forceinline__ void cpa_wait0() {
    asm volatile("cp.async.wait_group 0;" ::: "memory");
}

// =============================================================================
// Kernel A: GEMM, K-split, crossbar-optimized.
// grid (6,12,2) = 144 CTAs, 128 thr.  Tile 48x128, microtile 6 rows x 8 cols
// (cols = {tx*4..+3} U {64+tx*4..+3} for 2-phase LDS.128).
// Inner loop per k: 2 LDS.128 (B) + 6 LDS.32 (A) + 6 dup-movs + 24 FFMA2.
// cp.async double-buffered fills (A: 6x16B, B: 64x4B transpose).
// =============================================================================
#define GBM 48
#define GBN 128
#define GKT 64
#define APAD 68
#define BPAD 132
#define ABUF (GBM*APAD)          // 3264 floats
#define BBUF2 (GKT*BPAD)         // 8448 floats
#define TBUF (ABUF+BBUF2)        // 11712 floats / stage

__global__ __launch_bounds__(128, 1)
void gemm_kernel(const float* __restrict__ Am, const float* __restrict__ Aq,
                 const float* __restrict__ W)
{
    extern __shared__ __align__(16) float smG[];
    const unsigned smb = (unsigned)__cvta_generic_to_shared(smG);

    const int t   = threadIdx.x;
    const int tx  = t & 15;          // 16 col-groups
    const int ty  = t >> 4;          // 8 row-groups x 6 rows
    const int col0 = blockIdx.x * GBN;
    const int row0 = blockIdx.y * GBM;
    const int kz   = blockIdx.z;
    const int kbase = kz * KHALF;

    // A loader: 6 x (row, k-chunk) slots
    const float* aptr[6];
    int ar[6], ac[6];
#pragma unroll
    for (int j = 0; j < 6; j++) {
        const int idx = t + 128 * j;
        ar[j] = idx >> 4;
        ac[j] = (idx & 15) << 2;
        const int rg = row0 + ar[j];
        aptr[j] = ((rg < 64) ? (Am + (size_t)rg * IDIM)
                             : (Aq + (size_t)(rg - 64) * IDIM)) + kbase + ac[j];
    }

    // B loader: thread owns column t (0..127), all k of the tile
    const int gj = col0 + t;
    const int bn = gj / DC;
    const int bd = gj - bn * DC;
    const float* brow = W + ((size_t)bn * CC * DC + bd) * IDIM + kbase;

    // ---- async fill of one stage ----
    auto issue_tile = [&](int stage, int kt) {
        const unsigned Abase = smb + (unsigned)(stage * TBUF) * 4u;
        const unsigned Bbase = Abase + (unsigned)ABUF * 4u;
#pragma unroll
        for (int j = 0; j < 6; j++)
            cpa16(Abase + (unsigned)(ar[j] * APAD + ac[j]) * 4u, aptr[j] + kt);
#pragma unroll
        for (int k = 0; k < GKT; k++)
            cpa4(Bbase + (unsigned)(k * BPAD + t) * 4u, brow + kt + k);
        cpa_commit();
    };

    issue_tile(0, 0);
    cpa_wait0();
    __syncthreads();

    u64 acc[6][4];
#pragma unroll
    for (int i = 0; i < 6; i++)
#pragma unroll
        for (int c = 0; c < 4; c++) acc[i][c] = 0ull;

#pragma unroll 1
    for (int it = 0; it < KHALF / GKT; it++) {
        if (it < KHALF / GKT - 1)
            issue_tile((it + 1) & 1, (it + 1) * GKT);

        const float* As = smG + (it & 1) * TBUF;
        const float* Bs = As + ABUF;
#pragma unroll 16
        for (int k = 0; k < GKT; k++) {
            ulonglong2 b0 = *(const ulonglong2*)&Bs[k * BPAD + tx * 4];
            ulonglong2 b1 = *(const ulonglong2*)&Bs[k * BPAD + 64 + tx * 4];
#pragma unroll
            for (int i = 0; i < 6; i++) {
                const u64 ai = f2dup(As[(ty * 6 + i) * APAD + k]);
                acc[i][0] = ffma2(ai, b0.x, acc[i][0]);
                acc[i][1] = ffma2(ai, b0.y, acc[i][1]);
                acc[i][2] = ffma2(ai, b1.x, acc[i][2]);
                acc[i][3] = ffma2(ai, b1.y, acc[i][3]);
            }
        }
        if (it < KHALF / GKT - 1) cpa_wait0();
        __syncthreads();
    }

    float* hmP = g_hmP[kz];
    float* hqP = g_hqP[kz];
#pragma unroll
    for (int i = 0; i < 6; i++) {
        const int r = row0 + ty * 6 + i;
#pragma unroll
        for (int h = 0; h < 2; h++) {
            const int jb = col0 + h * 64 + tx * 4;
            float v0, v1, v2, v3;
            f2unpack(acc[i][2 * h + 0], v0, v1);
            f2unpack(acc[i][2 * h + 1], v2, v3);
            if (r < 64) {
                float vv[4] = {v0, v1, v2, v3};
#pragma unroll
                for (int cj = 0; cj < 4; cj++) {
                    const int j = jb + cj;
                    const int n = j / DC;
                    const int d = j - n * DC;
                    hmP[(n * CC + r) * DC + d] = vv[cj];
                }
            } else {
                float4 o; o.x = v0; o.y = v1; o.z = v2; o.w = v3;
                *(float4*)(hqP + (size_t)(r - 64) * ND + jb) = o;
            }
        }
    }
}

// =============================================================================
// Kernel B: merged prep + dotq (R14, unchanged).  grid 144.
// =============================================================================
__global__ __launch_bounds__(256, 1)
void prep_dotq_kernel(const float* __restrict__ Bb)
{
    extern __shared__ float smP[];
    const int bx = blockIdx.x, t = threadIdx.x;

    if (bx < 128) {
        const int ch = bx & 1, n = (bx >> 1) & 3, qt = bx >> 3;
        float* hq_s = smP;
        float* tm_s = smP + 32 * SQ194;
        float* red  = smP + 64 * SQ194;

        for (int i = t; i < 32 * 48; i += 256) {
            const int q = i / 48, d4 = (i % 48) << 2;
            const size_t off = (size_t)(qt * 32 + q) * ND + n * DC + d4;
            float4 a = *(const float4*)&g_hqP[0][off];
            float4 b = *(const float4*)&g_hqP[1][off];
            float4 v; v.x = a.x + b.x; v.y = a.y + b.y; v.z = a.z + b.z; v.w = a.w + b.w;
            *(float2*)&hq_s[q * SQ194 + d4]     = make_float2(v.x, v.y);
            *(float2*)&hq_s[q * SQ194 + d4 + 2] = make_float2(v.z, v.w);
        }
        for (int i = t; i < 32 * 48; i += 256) {
            const int c = i / 48, d4 = (i % 48) << 2;
            const size_t off = (size_t)(n * CC + ch * 32 + c) * DC + d4;
            float4 a = *(const float4*)&g_hmP[0][off];
            float4 b = *(const float4*)&g_hmP[1][off];
            float4 bb = *(const float4*)&Bb[off];
            float4 v;
            v.x = a.x + b.x + bb.x; v.y = a.y + b.y + bb.y;
            v.z = a.z + b.z + bb.z; v.w = a.w + b.w + bb.w;
            *(float2*)&tm_s[c * SQ194 + d4]     = make_float2(v.x, v.y);
            *(float2*)&tm_s[c * SQ194 + d4 + 2] = make_float2(v.z, v.w);
        }
        __syncthreads();

        const int qg = t & 15, cg = t >> 4;
        const float* hq0 = hq_s + qg * SQ194;
        const float* hq1 = hq_s + (qg + 16) * SQ194;
        const float* tm0 = tm_s + cg * SQ194;
        const float* tm1 = tm_s + (cg + 16) * SQ194;
        u64 a00 = 0ull, a01 = 0ull, a10 = 0ull, a11 = 0ull;
#pragma unroll 8
        for (int k2 = 0; k2 < 96; k2++) {
            const u64 h0 = *(const u64*)(hq0 + k2 * 2);
            const u64 h1 = *(const u64*)(hq1 + k2 * 2);
            const u64 t0 = *(const u64*)(tm0 + k2 * 2);
            const u64 t1 = *(const u64*)(tm1 + k2 * 2);
            a00 = ffma2(h0, t0, a00);
            a01 = ffma2(h0, t1, a01);
            a10 = ffma2(h1, t0, a10);
            a11 = ffma2(h1, t1, a11);
        }
        const int qb = qt * 32, cb = n * CC + ch * 32;
        float lo, hi;
        f2unpack(a00, lo, hi); g_dq0[(size_t)(qb + qg)      * 256 + cb + cg]      = lo + hi;
        f2unpack(a01, lo, hi); g_dq0[(size_t)(qb + qg)      * 256 + cb + cg + 16] = lo + hi;
        f2unpack(a10, lo, hi); g_dq0[(size_t)(qb + qg + 16) * 256 + cb + cg]      = lo + hi;
        f2unpack(a11, lo, hi); g_dq0[(size_t)(qb + qg + 16) * 256 + cb + cg + 16] = lo + hi;

        if (ch == 0) {
            const int q = t >> 3, seg = t & 7;
            float s = 0.f, sq = 0.f;
            const float* hp = hq_s + q * SQ194 + seg * 24;
#pragma unroll
            for (int k = 0; k < 12; k++) {
                float2 v = *(const float2*)(hp + 2 * k);
                s  += v.x + v.y;
                sq += v.x * v.x + v.y * v.y;
            }
            red[t] = s;
            red[256 + t] = sq;
            __syncthreads();
            if (t < 32) {
                float S = 0.f, SQ = 0.f;
#pragma unroll
                for (int c = 0; c < 8; c++) {
                    S  += red[t * 8 + c];
                    SQ += red[256 + t * 8 + c];
                }
                g_S1[(qt * 32 + t) * NC + n] = S;
                g_ss[(qt * 32 + t) * NC + n] = SQ;
            }
        }
    } else {
        const int idx = bx - 128;
        const int n = idx >> 2, quad = idx & 3;
        float* tm_s = smP;

        for (int i = t; i < CC * 48; i += 256) {
            const int r = i / 48, d4 = (i % 48) << 2;
            const size_t off = (size_t)(n * CC + r) * DC + d4;
            float4 a = *(const float4*)&g_hmP[0][off];
            float4 b = *(const float4*)&g_hmP[1][off];
            float4 bb = *(const float4*)&Bb[off];
            float4 v;
            v.x = a.x + b.x + bb.x; v.y = a.y + b.y + bb.y;
            v.z = a.z + b.z + bb.z; v.w = a.w + b.w + bb.w;
            *(float4*)&tm_s[r * TPAD + d4] = v;
        }
        __syncthreads();

        for (int i = t; i < 16 * 48; i += 256) {
            const int r = quad * 16 + i / 48;
            const int d4 = (i % 48) << 2;
            *(float4*)&g_hatm[(size_t)(n * CC + r) * DC + d4] =
                *(const float4*)&tm_s[r * TPAD + d4];
        }

        if (quad == 0 && t < CC) {
            const float* rp = tm_s + t * TPAD;
            float s = 0.f;
            for (int d = 0; d < DC; d += 4) {
                float4 v = *(const float4*)(rp + d);
                s += (v.x + v.y) + (v.z + v.w);
            }
            const float mu = s * (1.0f / DC);
            float ss = 0.f;
            for (int d = 0; d < DC; d += 4) {
                float4 v = *(const float4*)(rp + d);
                float e0 = v.x - mu, e1 = v.y - mu, e2 = v.z - mu, e3 = v.w - mu;
                ss += (e0 * e0 + e1 * e1) + (e2 * e2 + e3 * e3);
            }
            g_mu[n * CC + t] = mu; g_sxx[n * CC + t] = ss;
        }

        const int c1 = t & 63;
        const int c2b = quad * 16 + ((t >> 6) << 2);
        float acc[4] = {0.f, 0.f, 0.f, 0.f};
        for (int d4 = 0; d4 < DC; d4 += 4) {
            float4 x = *(const float4*)&tm_s[c1 * TPAD + d4];
#pragma unroll
            for (int j = 0; j < 4; j++) {
                float4 y = *(const float4*)&tm_s[(c2b + j) * TPAD + d4];
                acc[j] += (x.x * y.x + x.y * y.y) + (x.z * y.z + x.w * y.w);
            }
        }
        float4 o; o.x = acc[0]; o.y = acc[1]; o.z = acc[2]; o.w = acc[3];
        *(float4*)&g_G[(n * CC + c1) * CC + c2b] = o;
    }
}

// =============================================================================
// Kernel C: MERGED route + out (R13/R14, unchanged).  grid 128 x 256.
// =============================================================================
__global__ __launch_bounds__(256, 1)
void route_out_kernel(float* __restrict__ out)
{
    extern __shared__ float smD[];
    float* G_s  = smD;
    float* co_t = smD + NC * CC * GPAD;

    const int t = threadIdx.x, lane = t & 31, w = t >> 5;
    const int q0 = blockIdx.x * 4;

    for (int i = t; i < NC * CC * 16; i += 256) {
        const int row = i >> 4, c4 = (i & 15) << 2;
        *(float4*)&G_s[row * GPAD + c4] = *(const float4*)&g_G[row * CC + c4];
    }
    __syncthreads();

    if (w < 4) {
        const int q = q0 + w;
        float mu[NC][2], sxx[NC][2], dq[NC][2], a[NC][2], p[NC][2], co[NC][2];
        float S1[NC], ss[NC];
#pragma unroll
        for (int n = 0; n < NC; n++) {
#pragma unroll
            for (int j = 0; j < 2; j++) {
                const int idx = n * CC + lane + 32 * j;
                mu[n][j]  = g_mu[idx];
                sxx[n][j] = g_sxx[idx];
                dq[n][j]  = g_dq0[(size_t)q * 256 + idx];
                a[n][j]   = 0.f;
            }
            S1[n] = g_S1[q * NC + n];
            ss[n] = g_ss[q * NC + n];
            const float syy = ss[n] - S1[n] * S1[n] * (1.0f / DC);
#pragma unroll
            for (int j = 0; j < 2; j++)
                p[n][j] = tanhf(-(dq[n][j] - mu[n][j] * S1[n])
                                * rsqrtf(sxx[n][j] * syy + EPSF));
        }

#pragma unroll 1
        for (int it = 0; it < 3; it++) {
#pragma unroll
            for (int j = 0; j < 2; j++) {
                float mx = fmaxf(fmaxf(a[0][j], a[1][j]), fmaxf(a[2][j], a[3][j]));
                float e0 = expf(a[0][j] - mx), e1 = expf(a[1][j] - mx);
                float e2 = expf(a[2][j] - mx), e3 = expf(a[3][j] - mx);
                float inv = 1.0f / (e0 + e1 + e2 + e3);
                co[0][j] = e0 * inv + p[0][j];
                co[1][j] = e1 * inv + p[1][j];
                co[2][j] = e2 * inv + p[2][j];
                co[3][j] = e3 * inv + p[3][j];
            }
#pragma unroll
            for (int n = 0; n < NC; n++) {
                co_t[(n * CC + lane) * 4 + w]      = co[n][0];
                co_t[(n * CC + lane + 32) * 4 + w] = co[n][1];
            }
            __syncwarp();

            float gc[NC][2];
#pragma unroll
            for (int n = 0; n < NC; n++) {
                const float* r0 = &G_s[(n * CC + lane) * GPAD];
                const float* r1 = &G_s[(n * CC + lane + 32) * GPAD];
                const float* cw = co_t + n * CC * 4 + w;
                float a0 = 0.f, a1 = 0.f;
#pragma unroll
                for (int c = 0; c < CC; c += 4) {
                    float4 g0 = *(const float4*)(r0 + c);
                    float4 g1 = *(const float4*)(r1 + c);
                    const float c0 = cw[(c + 0) * 4];
                    const float c1 = cw[(c + 1) * 4];
                    const float c2 = cw[(c + 2) * 4];
                    const float c3 = cw[(c + 3) * 4];
                    a0 += (c0 * g0.x + c1 * g0.y) + (c2 * g0.z + c3 * g0.w);
                    a1 += (c0 * g1.x + c1 * g1.y) + (c2 * g1.z + c3 * g1.w);
                }
                gc[n][0] = a0; gc[n][1] = a1;
            }

            float rS[NC], rD[NC], rM[NC];
#pragma unroll
            for (int n = 0; n < NC; n++) {
                rS[n] = co[n][0] * gc[n][0] + co[n][1] * gc[n][1];
                rD[n] = co[n][0] * dq[n][0] + co[n][1] * dq[n][1];
                rM[n] = co[n][0] * mu[n][0] + co[n][1] * mu[n][1];
            }
#pragma unroll
            for (int o = 16; o > 0; o >>= 1)
#pragma unroll
                for (int n = 0; n < NC; n++) {
                    rS[n] += __shfl_xor_sync(0xffffffffu, rS[n], o);
                    rD[n] += __shfl_xor_sync(0xffffffffu, rD[n], o);
                    rM[n] += __shfl_xor_sync(0xffffffffu, rM[n], o);
                }

            if (it == 2) {
#pragma unroll
                for (int n = 0; n < NC; n++) {
                    const float s = rS[n];
                    const float scale = s / ((1.0f + s) * sqrtf(s + EPSF));
                    co_t[(n * CC + lane) * 4 + w]      = co[n][0] * scale;
                    co_t[(n * CC + lane + 32) * 4 + w] = co[n][1] * scale;
                }
                break;
            }

#pragma unroll
            for (int n = 0; n < NC; n++) {
                const float s = rS[n];
                const float scale = s / ((1.0f + s) * sqrtf(s + EPSF));
                const float S1n = 0.5f * (S1[n] + scale * (float)DC * rM[n]);
                const float ssn = 0.25f * (ss[n] + 2.0f * scale * rD[n]
                                           + scale * scale * s);
#pragma unroll
                for (int j = 0; j < 2; j++) {
                    const float ag = scale * gc[n][j];
                    a[n][j] += p[n][j] * ag;
                    dq[n][j] = 0.5f * (dq[n][j] + ag);
                }
                S1[n] = S1n; ss[n] = ssn;
                const float syy = ssn - S1n * S1n * (1.0f / DC);
#pragma unroll
                for (int j = 0; j < 2; j++)
                    p[n][j] = tanhf(-(dq[n][j] - mu[n][j] * S1n)
                                    * rsqrtf(sxx[n][j] * syy + EPSF));
            }
            __syncwarp();
        }
    }
    __syncthreads();

#pragma unroll
    for (int rep = 0; rep < 2; rep++) {
        const int s = t + rep * 256;
        if (s < NC * 96) {
            const int n  = s / 96;
            const int dp = s - n * 96;
            const float* tmb = g_hatm + (size_t)(n * CC) * DC + dp * 2;
            const float* cob = co_t + n * CC * 4;
            u64 a0 = 0ull, a1 = 0ull, a2 = 0ull, a3 = 0ull;
#pragma unroll 8
            for (int c = 0; c < CC; c++) {
                const u64 tv = *(const u64*)(tmb + (size_t)c * DC);
                float4 cv = *(const float4*)(cob + c * 4);
                a0 = ffma2(f2dup(cv.x), tv, a0);
                a1 = ffma2(f2dup(cv.y), tv, a1);
                a2 = ffma2(f2dup(cv.z), tv, a2);
                a3 = ffma2(f2dup(cv.w), tv, a3);
            }
            float lo, hi;
            float* ob = out + (size_t)q0 * ND + n * DC + dp * 2;
            f2unpack(a0, lo, hi); *(float2*)(ob)          = make_float2(lo, hi);
            f2unpack(a1, lo, hi); *(float2*)(ob + ND)     = make_float2(lo, hi);
            f2unpack(a2, lo, hi); *(float2*)(ob + 2 * ND) = make_float2(lo, hi);
            f2unpack(a3, lo, hi); *(float2*)(ob + 3 * ND) = make_float2(lo, hi);
        }
    }
}

// =============================================================================
// launch
// =============================================================================
extern "C" void kernel_launch(void* const* d_in, const int* in_sizes, int n_in,
                              void* d_out, int out_size)
{
    const float* m = (const float*)d_in[0];
    const float* q = (const float*)d_in[1];
    const float* W = (const float*)d_in[2];
    const float* b = (const float*)d_in[3];
    float* out = (float*)d_out;
    (void)in_sizes; (void)n_in; (void)out_size;

    const int smG = 2 * TBUF * 4;                           // 93696
    const int smP = (64 * SQ194 + 512) * 4;                 // 51712
    const int smD = (NC * CC * GPAD + NC * CC * 4) * 4;     // 73728
    cudaFuncSetAttribute(gemm_kernel, cudaFuncAttributeMaxDynamicSharedMemorySize, smG);
    cudaFuncSetAttribute(prep_dotq_kernel, cudaFuncAttributeMaxDynamicSharedMemorySize, smP);
    cudaFuncSetAttribute(route_out_kernel, cudaFuncAttributeMaxDynamicSharedMemorySize, smD);

    gemm_kernel<<<dim3(6, 12, 2), 128, smG>>>(m, q, W);
    prep_dotq_kernel<<<144, 256, smP>>>(b);
    route_out_kernel<<<128, 256, smD>>>(out);
}

// round 16
// speedup vs baseline: 1.3736x; 1.3736x over previous
#include <cuda_runtime.h>
#include <cstdint>
#include <cstddef>

#define NC    4
#define CC    64
#define DC    192
#define TPAD  196
#define GPAD  68
#define QQ    512
#define ND    (NC*DC)
#define IDIM  768
#define EPSF  1e-8f
#define SQ194 194
#define NKS   4
#define KQ    192          // K per split

__device__ float g_hmP[NKS][NC*CC*DC];
__device__ float g_hqP[NKS][QQ*ND];
__device__ float g_hatm[NC*CC*DC];
__device__ float g_G[NC*CC*CC];
__device__ float g_mu[NC*CC];
__device__ float g_sxx[NC*CC];
__device__ float g_dq0[QQ*NC*CC];
__device__ float g_S1[QQ*NC];
__device__ float g_ss[QQ*NC];

typedef unsigned long long u64;
__device__ __forceinline__ void f2unpack(u64 v, float& lo, float& hi) {
    asm("mov.b64 {%0, %1}, %2;" : "=f"(lo), "=f"(hi) : "l"(v));
}
__device__ __forceinline__ u64 f2dup(float a) {
    u64 r;
    asm("mov.b64 %0, {%1, %1};" : "=l"(r) : "f"(a));
    return r;
}
__device__ __forceinline__ u64 ffma2(u64 a, u64 b, u64 c) {
    u64 d;
    asm("fma.rn.f32x2 %0, %1, %2, %3;" : "=l"(d) : "l"(a), "l"(b), "l"(c));
    return d;
}

// =============================================================================
// Kernel A: GEMM.  grid (6 colTiles, 6 rowTiles, 4 kSplit) = 144 CTAs, 256 thr.
// Tile 96x128, microtile 6x8 (1.17 B/FMA crossbar), GKT=64, sync fills (R13 style).
// =============================================================================
#define GBM 96
#define GBN 128
#define GKT 64
#define APAD 68
#define BPAD 132

__global__ __launch_bounds__(256, 1)
void gemm_kernel(const float* __restrict__ Am, const float* __restrict__ Aq,
                 const float* __restrict__ W)
{
    extern __shared__ __align__(16) float smG[];
    float* As = smG;                 // [96][APAD]
    float* Bs = smG + GBM * APAD;    // [64][BPAD]

    const int t   = threadIdx.x;
    const int tx  = t & 15;          // 16 col-groups (x2 halves)
    const int ty  = t >> 4;          // 16 row-groups x 6 rows
    const int col0 = blockIdx.x * GBN;
    const int row0 = blockIdx.y * GBM;
    const int kbase = blockIdx.z * KQ;

    // A loader: 6 slots (96 rows x 16 float4)
    const float* aptr[6];
    int ar[6], ac[6];
#pragma unroll
    for (int j = 0; j < 6; j++) {
        const int idx = t + 256 * j;
        ar[j] = idx >> 4;
        ac[j] = (idx & 15) << 2;
        const int rg = row0 + ar[j];
        aptr[j] = ((rg < 64) ? (Am + (size_t)rg * IDIM)
                             : (Aq + (size_t)(rg - 64) * IDIM)) + kbase + ac[j];
    }

    // B loader: col = t&127, k-half = (t>>7)*32; 8 float4 along k
    const int bcol = t & 127;
    const int bk0  = (t >> 7) << 5;
    const int gj = col0 + bcol;
    const int bn = gj / DC;
    const int bd = gj - bn * DC;
    const float* brow = W + ((size_t)bn * CC * DC + bd) * IDIM + kbase + bk0;

    u64 acc[6][4];
#pragma unroll
    for (int i = 0; i < 6; i++)
#pragma unroll
        for (int c = 0; c < 4; c++) acc[i][c] = 0ull;

#pragma unroll 1
    for (int kt = 0; kt < KQ; kt += GKT) {
#pragma unroll
        for (int j = 0; j < 6; j++) {
            float4 a = *(const float4*)(aptr[j] + kt);
            *(float4*)&As[ar[j] * APAD + ac[j]] = a;
        }
#pragma unroll
        for (int i = 0; i < 8; i++) {
            float4 b = *(const float4*)(brow + kt + 4 * i);
            const int k = bk0 + 4 * i;
            Bs[(k + 0) * BPAD + bcol] = b.x;
            Bs[(k + 1) * BPAD + bcol] = b.y;
            Bs[(k + 2) * BPAD + bcol] = b.z;
            Bs[(k + 3) * BPAD + bcol] = b.w;
        }
        __syncthreads();
#pragma unroll 16
        for (int k = 0; k < GKT; k++) {
            ulonglong2 b0 = *(const ulonglong2*)&Bs[k * BPAD + (tx << 2)];
            ulonglong2 b1 = *(const ulonglong2*)&Bs[k * BPAD + 64 + (tx << 2)];
#pragma unroll
            for (int i = 0; i < 6; i++) {
                const u64 ai = f2dup(As[(ty * 6 + i) * APAD + k]);
                acc[i][0] = ffma2(ai, b0.x, acc[i][0]);
                acc[i][1] = ffma2(ai, b0.y, acc[i][1]);
                acc[i][2] = ffma2(ai, b1.x, acc[i][2]);
                acc[i][3] = ffma2(ai, b1.y, acc[i][3]);
            }
        }
        __syncthreads();
    }

    float* hmP = g_hmP[blockIdx.z];
    float* hqP = g_hqP[blockIdx.z];
#pragma unroll
    for (int i = 0; i < 6; i++) {
        const int r = row0 + ty * 6 + i;
#pragma unroll
        for (int h = 0; h < 2; h++) {
            const int jb = col0 + h * 64 + (tx << 2);
            float v0, v1, v2, v3;
            f2unpack(acc[i][2 * h + 0], v0, v1);
            f2unpack(acc[i][2 * h + 1], v2, v3);
            if (r < 64) {
                float vv[4] = {v0, v1, v2, v3};
#pragma unroll
                for (int cj = 0; cj < 4; cj++) {
                    const int j = jb + cj;
                    const int n = j / DC;
                    const int d = j - n * DC;
                    hmP[(n * CC + r) * DC + d] = vv[cj];
                }
            } else {
                float4 o; o.x = v0; o.y = v1; o.z = v2; o.w = v3;
                *(float4*)(hqP + (size_t)(r - 64) * ND + jb) = o;
            }
        }
    }
}

// combine helpers
__device__ __forceinline__ float4 comb4_hq(size_t off) {
    float4 a = *(const float4*)&g_hqP[0][off];
    float4 b = *(const float4*)&g_hqP[1][off];
    float4 c = *(const float4*)&g_hqP[2][off];
    float4 d = *(const float4*)&g_hqP[3][off];
    float4 v;
    v.x = (a.x + b.x) + (c.x + d.x);
    v.y = (a.y + b.y) + (c.y + d.y);
    v.z = (a.z + b.z) + (c.z + d.z);
    v.w = (a.w + b.w) + (c.w + d.w);
    return v;
}
__device__ __forceinline__ float4 comb4_hm(size_t off, const float* __restrict__ Bb) {
    float4 a = *(const float4*)&g_hmP[0][off];
    float4 b = *(const float4*)&g_hmP[1][off];
    float4 c = *(const float4*)&g_hmP[2][off];
    float4 d = *(const float4*)&g_hmP[3][off];
    float4 e = *(const float4*)&Bb[off];
    float4 v;
    v.x = (a.x + b.x) + (c.x + d.x) + e.x;
    v.y = (a.y + b.y) + (c.y + d.y) + e.y;
    v.z = (a.z + b.z) + (c.z + d.z) + e.z;
    v.w = (a.w + b.w) + (c.w + d.w) + e.w;
    return v;
}

// =============================================================================
// Kernel B: merged prep + dotq (R13 structure; 4-way K combine).  grid 144.
// =============================================================================
__global__ __launch_bounds__(256, 1)
void prep_dotq_kernel(const float* __restrict__ Bb)
{
    extern __shared__ float smP[];
    const int bx = blockIdx.x, t = threadIdx.x;

    if (bx < 128) {
        const int ch = bx & 1, n = (bx >> 1) & 3, qt = bx >> 3;
        float* hq_s = smP;
        float* tm_s = smP + 32 * SQ194;
        float* red  = smP + 64 * SQ194;

        for (int i = t; i < 32 * 48; i += 256) {
            const int q = i / 48, d4 = (i % 48) << 2;
            float4 v = comb4_hq((size_t)(qt * 32 + q) * ND + n * DC + d4);
            *(float2*)&hq_s[q * SQ194 + d4]     = make_float2(v.x, v.y);
            *(float2*)&hq_s[q * SQ194 + d4 + 2] = make_float2(v.z, v.w);
        }
        for (int i = t; i < 32 * 48; i += 256) {
            const int c = i / 48, d4 = (i % 48) << 2;
            float4 v = comb4_hm((size_t)(n * CC + ch * 32 + c) * DC + d4, Bb);
            *(float2*)&tm_s[c * SQ194 + d4]     = make_float2(v.x, v.y);
            *(float2*)&tm_s[c * SQ194 + d4 + 2] = make_float2(v.z, v.w);
        }
        __syncthreads();

        const int qg = t & 15, cg = t >> 4;
        const float* hq0 = hq_s + qg * SQ194;
        const float* hq1 = hq_s + (qg + 16) * SQ194;
        const float* tm0 = tm_s + cg * SQ194;
        const float* tm1 = tm_s + (cg + 16) * SQ194;
        u64 a00 = 0ull, a01 = 0ull, a10 = 0ull, a11 = 0ull;
#pragma unroll 8
        for (int k2 = 0; k2 < 96; k2++) {
            const u64 h0 = *(const u64*)(hq0 + k2 * 2);
            const u64 h1 = *(const u64*)(hq1 + k2 * 2);
            const u64 t0 = *(const u64*)(tm0 + k2 * 2);
            const u64 t1 = *(const u64*)(tm1 + k2 * 2);
            a00 = ffma2(h0, t0, a00);
            a01 = ffma2(h0, t1, a01);
            a10 = ffma2(h1, t0, a10);
            a11 = ffma2(h1, t1, a11);
        }
        const int qb = qt * 32, cb = n * CC + ch * 32;
        float lo, hi;
        f2unpack(a00, lo, hi); g_dq0[(size_t)(qb + qg)      * 256 + cb + cg]      = lo + hi;
        f2unpack(a01, lo, hi); g_dq0[(size_t)(qb + qg)      * 256 + cb + cg + 16] = lo + hi;
        f2unpack(a10, lo, hi); g_dq0[(size_t)(qb + qg + 16) * 256 + cb + cg]      = lo + hi;
        f2unpack(a11, lo, hi); g_dq0[(size_t)(qb + qg + 16) * 256 + cb + cg + 16] = lo + hi;

        if (ch == 0) {
            const int q = t >> 3, seg = t & 7;
            float s = 0.f, sq = 0.f;
            const float* hp = hq_s + q * SQ194 + seg * 24;
#pragma unroll
            for (int k = 0; k < 12; k++) {
                float2 v = *(const float2*)(hp + 2 * k);
                s  += v.x + v.y;
                sq += v.x * v.x + v.y * v.y;
            }
            red[t] = s;
            red[256 + t] = sq;
            __syncthreads();
            if (t < 32) {
                float S = 0.f, SQ = 0.f;
#pragma unroll
                for (int c = 0; c < 8; c++) {
                    S  += red[t * 8 + c];
                    SQ += red[256 + t * 8 + c];
                }
                g_S1[(qt * 32 + t) * NC + n] = S;
                g_ss[(qt * 32 + t) * NC + n] = SQ;
            }
        }
    } else {
        const int idx = bx - 128;
        const int n = idx >> 2, quad = idx & 3;
        float* tm_s = smP;

        for (int i = t; i < CC * 48; i += 256) {
            const int r = i / 48, d4 = (i % 48) << 2;
            float4 v = comb4_hm((size_t)(n * CC + r) * DC + d4, Bb);
            *(float4*)&tm_s[r * TPAD + d4] = v;
        }
        __syncthreads();

        for (int i = t; i < 16 * 48; i += 256) {
            const int r = quad * 16 + i / 48;
            const int d4 = (i % 48) << 2;
            *(float4*)&g_hatm[(size_t)(n * CC + r) * DC + d4] =
                *(const float4*)&tm_s[r * TPAD + d4];
        }

        if (quad == 0 && t < CC) {
            const float* rp = tm_s + t * TPAD;
            float s = 0.f;
            for (int d = 0; d < DC; d += 4) {
                float4 v = *(const float4*)(rp + d);
                s += (v.x + v.y) + (v.z + v.w);
            }
            const float mu = s * (1.0f / DC);
            float ss = 0.f;
            for (int d = 0; d < DC; d += 4) {
                float4 v = *(const float4*)(rp + d);
                float e0 = v.x - mu, e1 = v.y - mu, e2 = v.z - mu, e3 = v.w - mu;
                ss += (e0 * e0 + e1 * e1) + (e2 * e2 + e3 * e3);
            }
            g_mu[n * CC + t] = mu; g_sxx[n * CC + t] = ss;
        }

        const int c1 = t & 63;
        const int c2b = quad * 16 + ((t >> 6) << 2);
        float acc[4] = {0.f, 0.f, 0.f, 0.f};
        for (int d4 = 0; d4 < DC; d4 += 4) {
            float4 x = *(const float4*)&tm_s[c1 * TPAD + d4];
#pragma unroll
            for (int j = 0; j < 4; j++) {
                float4 y = *(const float4*)&tm_s[(c2b + j) * TPAD + d4];
                acc[j] += (x.x * y.x + x.y * y.y) + (x.z * y.z + x.w * y.w);
            }
        }
        float4 o; o.x = acc[0]; o.y = acc[1]; o.z = acc[2]; o.w = acc[3];
        *(float4*)&g_G[(n * CC + c1) * CC + c2b] = o;
    }
}

// =============================================================================
// Kernel C: MERGED route + out (unchanged).  grid 128 x 256.
// =============================================================================
__global__ __launch_bounds__(256, 1)
void route_out_kernel(float* __restrict__ out)
{
    extern __shared__ float smD[];
    float* G_s  = smD;
    float* co_t = smD + NC * CC * GPAD;

    const int t = threadIdx.x, lane = t & 31, w = t >> 5;
    const int q0 = blockIdx.x * 4;

    for (int i = t; i < NC * CC * 16; i += 256) {
        const int row = i >> 4, c4 = (i & 15) << 2;
        *(float4*)&G_s[row * GPAD + c4] = *(const float4*)&g_G[row * CC + c4];
    }
    __syncthreads();

    if (w < 4) {
        const int q = q0 + w;
        float mu[NC][2], sxx[NC][2], dq[NC][2], a[NC][2], p[NC][2], co[NC][2];
        float S1[NC], ss[NC];
#pragma unroll
        for (int n = 0; n < NC; n++) {
#pragma unroll
            for (int j = 0; j < 2; j++) {
                const int idx = n * CC + lane + 32 * j;
                mu[n][j]  = g_mu[idx];
                sxx[n][j] = g_sxx[idx];
                dq[n][j]  = g_dq0[(size_t)q * 256 + idx];
                a[n][j]   = 0.f;
            }
            S1[n] = g_S1[q * NC + n];
            ss[n] = g_ss[q * NC + n];
            const float syy = ss[n] - S1[n] * S1[n] * (1.0f / DC);
#pragma unroll
            for (int j = 0; j < 2; j++)
                p[n][j] = tanhf(-(dq[n][j] - mu[n][j] * S1[n])
                                * rsqrtf(sxx[n][j] * syy + EPSF));
        }

#pragma unroll 1
        for (int it = 0; it < 3; it++) {
#pragma unroll
            for (int j = 0; j < 2; j++) {
                float mx = fmaxf(fmaxf(a[0][j], a[1][j]), fmaxf(a[2][j], a[3][j]));
                float e0 = expf(a[0][j] - mx), e1 = expf(a[1][j] - mx);
                float e2 = expf(a[2][j] - mx), e3 = expf(a[3][j] - mx);
                float inv = 1.0f / (e0 + e1 + e2 + e3);
                co[0][j] = e0 * inv + p[0][j];
                co[1][j] = e1 * inv + p[1][j];
                co[2][j] = e2 * inv + p[2][j];
                co[3][j] = e3 * inv + p[3][j];
            }
#pragma unroll
            for (int n = 0; n < NC; n++) {
                co_t[(n * CC + lane) * 4 + w]      = co[n][0];
                co_t[(n * CC + lane + 32) * 4 + w] = co[n][1];
            }
            __syncwarp();

            float gc[NC][2];
#pragma unroll
            for (int n = 0; n < NC; n++) {
                const float* r0 = &G_s[(n * CC + lane) * GPAD];
                const float* r1 = &G_s[(n * CC + lane + 32) * GPAD];
                const float* cw = co_t + n * CC * 4 + w;
                float a0 = 0.f, a1 = 0.f;
#pragma unroll
                for (int c = 0; c < CC; c += 4) {
                    float4 g0 = *(const float4*)(r0 + c);
                    float4 g1 = *(const float4*)(r1 + c);
                    const float c0 = cw[(c + 0) * 4];
                    const float c1 = cw[(c + 1) * 4];
                    const float c2 = cw[(c + 2) * 4];
                    const float c3 = cw[(c + 3) * 4];
                    a0 += (c0 * g0.x + c1 * g0.y) + (c2 * g0.z + c3 * g0.w);
                    a1 += (c0 * g1.x + c1 * g1.y) + (c2 * g1.z + c3 * g1.w);
                }
                gc[n][0] = a0; gc[n][1] = a1;
            }

            float rS[NC], rD[NC], rM[NC];
#pragma unroll
            for (int n = 0; n < NC; n++) {
                rS[n] = co[n][0] * gc[n][0] + co[n][1] * gc[n][1];
                rD[n] = co[n][0] * dq[n][0] + co[n][1] * dq[n][1];
                rM[n] = co[n][0] * mu[n][0] + co[n][1] * mu[n][1];
            }
#pragma unroll
            for (int o = 16; o > 0; o >>= 1)
#pragma unroll
                for (int n = 0; n < NC; n++) {
                    rS[n] += __shfl_xor_sync(0xffffffffu, rS[n], o);
                    rD[n] += __shfl_xor_sync(0xffffffffu, rD[n], o);
                    rM[n] += __shfl_xor_sync(0xffffffffu, rM[n], o);
                }

            if (it == 2) {
#pragma unroll
                for (int n = 0; n < NC; n++) {
                    const float s = rS[n];
                    const float scale = s / ((1.0f + s) * sqrtf(s + EPSF));
                    co_t[(n * CC + lane) * 4 + w]      = co[n][0] * scale;
                    co_t[(n * CC + lane + 32) * 4 + w] = co[n][1] * scale;
                }
                break;
            }

#pragma unroll
            for (int n = 0; n < NC; n++) {
                const float s = rS[n];
                const float scale = s / ((1.0f + s) * sqrtf(s + EPSF));
                const float S1n = 0.5f * (S1[n] + scale * (float)DC * rM[n]);
                const float ssn = 0.25f * (ss[n] + 2.0f * scale * rD[n]
                                           + scale * scale * s);
#pragma unroll
                for (int j = 0; j < 2; j++) {
                    const float ag = scale * gc[n][j];
                    a[n][j] += p[n][j] * ag;
                    dq[n][j] = 0.5f * (dq[n][j] + ag);
                }
                S1[n] = S1n; ss[n] = ssn;
                const float syy = ssn - S1n * S1n * (1.0f / DC);
#pragma unroll
                for (int j = 0; j < 2; j++)
                    p[n][j] = tanhf(-(dq[n][j] - mu[n][j] * S1n)
                                    * rsqrtf(sxx[n][j] * syy + EPSF));
            }
            __syncwarp();
        }
    }
    __syncthreads();

#pragma unroll
    for (int rep = 0; rep < 2; rep++) {
        const int s = t + rep * 256;
        if (s < NC * 96) {
            const int n  = s / 96;
            const int dp = s - n * 96;
            const float* tmb = g_hatm + (size_t)(n * CC) * DC + dp * 2;
            const float* cob = co_t + n * CC * 4;
            u64 a0 = 0ull, a1 = 0ull, a2 = 0ull, a3 = 0ull;
#pragma unroll 8
            for (int c = 0; c < CC; c++) {
                const u64 tv = *(const u64*)(tmb + (size_t)c * DC);
                float4 cv = *(const float4*)(cob + c * 4);
                a0 = ffma2(f2dup(cv.x), tv, a0);
                a1 = ffma2(f2dup(cv.y), tv, a1);
                a2 = ffma2(f2dup(cv.z), tv, a2);
                a3 = ffma2(f2dup(cv.w), tv, a3);
            }
            float lo, hi;
            float* ob = out + (size_t)q0 * ND + n * DC + dp * 2;
            f2unpack(a0, lo, hi); *(float2*)(ob)          = make_float2(lo, hi);
            f2unpack(a1, lo, hi); *(float2*)(ob + ND)     = make_float2(lo, hi);
            f2unpack(a2, lo, hi); *(float2*)(ob + 2 * ND) = make_float2(lo, hi);
            f2unpack(a3, lo, hi); *(float2*)(ob + 3 * ND) = make_float2(lo, hi);
        }
    }
}

// =============================================================================
// launch
// =============================================================================
extern "C" void kernel_launch(void* const* d_in, const int* in_sizes, int n_in,
                              void* d_out, int out_size)
{
    const float* m = (const float*)d_in[0];
    const float* q = (const float*)d_in[1];
    const float* W = (const float*)d_in[2];
    const float* b = (const float*)d_in[3];
    float* out = (float*)d_out;
    (void)in_sizes; (void)n_in; (void)out_size;

    const int smG = (GBM * APAD + GKT * BPAD) * 4;          // 59904
    const int smP = (64 * SQ194 + 512) * 4;                 // 51712
    const int smD = (NC * CC * GPAD + NC * CC * 4) * 4;     // 73728
    cudaFuncSetAttribute(gemm_kernel, cudaFuncAttributeMaxDynamicSharedMemorySize, smG);
    cudaFuncSetAttribute(prep_dotq_kernel, cudaFuncAttributeMaxDynamicSharedMemorySize, smP);
    cudaFuncSetAttribute(route_out_kernel, cudaFuncAttributeMaxDynamicSharedMemorySize, smD);

    gemm_kernel<<<dim3(6, 6, 4), 256, smG>>>(m, q, W);
    prep_dotq_kernel<<<144, 256, smP>>>(b);
    route_out_kernel<<<128, 256, smD>>>(out);
}